// round 1
// baseline (speedup 1.0000x reference)
#include <cuda_runtime.h>

// GTConvAE on GB300.
// Identity used: S = sum_{a,b in {0,1}} s[a][b] * kron(St^a, Sg^b)  (St = cyclic delay)
//  => S^k x[tau] = sum_{a,b=0..2} c_k[a][b] * Sg^b x[(tau-a) mod t]
// with c_0 = delta(0,0), c_1 = s, c_2 = s (*) s (2D convolution of coeffs).
// So each conv layer = two GEMMs (Sg @ X, Sg^2 @ X) + a 9-term weighted combine
// with folded filters H[o][i][a][b] = sum_k h[o][i][k] * c_k[a][b].

#define NN 192   // nodes
#define TT 32    // timesteps

// ------------------------- scratch (device globals; no allocation) ------------
__device__ float g_Sg2[NN * NN];        // Sg @ Sg, row-major
__device__ float g_G1[256 * NN];        // Sg  @ act   layout [col j][n], j = tau*Ci+i
__device__ float g_G2[256 * NN];        // Sg2 @ act
__device__ float g_actA[256 * NN];      // e1 output (16t x 16c x 192n), reused for d1 output
__device__ float g_actB[256 * NN];      // e2 output (8t x 32c x 192n)

// ------------------------- GEMM: C[m,j] = sum_k A[m,k] * B[k,j] ---------------
// A: 192x192 row-major (selected by blockIdx.z: z=0 -> A0/C0, z=1 -> A1/C1).
// B element at B[k*sK + j*sJ].  C element at C[m*osM + j*osJ].
// M = 192 (grid.y = 6), J multiple of 32 (grid.x = J/32).
__global__ __launch_bounds__(256) void gemm192(
    const float* __restrict__ A0, const float* __restrict__ A1,
    const float* __restrict__ B,
    float* __restrict__ C0, float* __restrict__ C1,
    int J, int sK, int sJ, int osM, int osJ)
{
    const float* A = blockIdx.z ? A1 : A0;
    float* C = blockIdx.z ? C1 : C0;

    __shared__ float As[32][34];  // [k][m], pad 34 keeps float2 alignment
    __shared__ float Bs[32][34];  // [k][j]

    const int tx = threadIdx.x;             // 0..15 (cols)
    const int ty = threadIdx.y;             // 0..15 (rows)
    const int tid = ty * 16 + tx;
    const int m0 = blockIdx.y * 32;
    const int j0 = blockIdx.x * 32;

    float acc00 = 0.f, acc01 = 0.f, acc10 = 0.f, acc11 = 0.f;

    for (int k0 = 0; k0 < NN; k0 += 32) {
        // load A tile: coalesced along k (A row-major)
        #pragma unroll
        for (int r = 0; r < 4; r++) {
            int idx = tid + 256 * r;
            int ml = idx >> 5, kl = idx & 31;
            As[kl][ml] = A[(m0 + ml) * NN + (k0 + kl)];
        }
        // load B tile: pick the coalesced mapping based on which stride is 1
        #pragma unroll
        for (int r = 0; r < 4; r++) {
            int idx = tid + 256 * r;
            int hi = idx >> 5, lo = idx & 31;
            int kl, jl;
            if (sK == 1) { kl = lo; jl = hi; } else { kl = hi; jl = lo; }
            Bs[kl][jl] = B[(k0 + kl) * sK + (j0 + jl) * sJ];
        }
        __syncthreads();
        #pragma unroll
        for (int kk = 0; kk < 32; kk++) {
            float2 a = *(const float2*)(&As[kk][2 * ty]);
            float2 b = *(const float2*)(&Bs[kk][2 * tx]);
            acc00 += a.x * b.x; acc01 += a.x * b.y;
            acc10 += a.y * b.x; acc11 += a.y * b.y;
        }
        __syncthreads();
    }
    const int m = m0 + 2 * ty, j = j0 + 2 * tx;
    C[(m + 0) * osM + (j + 0) * osJ] = acc00;
    C[(m + 0) * osM + (j + 1) * osJ] = acc01;
    C[(m + 1) * osM + (j + 0) * osJ] = acc10;
    C[(m + 1) * osM + (j + 1) * osJ] = acc11;
}

// ------------------------- folded filter table --------------------------------
// c_k[a][b]: k=0: delta(a==0,b==0); k=1: s[a][b] (a,b<2); k=2: (s * s)[a][b].
__device__ __forceinline__ float fold_H(const float* __restrict__ h3,
                                        const float sv[4], int a, int b)
{
    float c0 = (a == 0 && b == 0) ? 1.f : 0.f;
    float c1 = (a < 2 && b < 2) ? sv[a * 2 + b] : 0.f;
    float c2 = 0.f;
    #pragma unroll
    for (int a1 = 0; a1 < 2; a1++)
        #pragma unroll
        for (int b1 = 0; b1 < 2; b1++) {
            int a2 = a - a1, b2 = b - b1;
            if (a2 >= 0 && a2 < 2 && b2 >= 0 && b2 < 2)
                c2 += sv[a1 * 2 + b1] * sv[a2 * 2 + b2];
        }
    return h3[0] * c0 + h3[1] * c1 + h3[2] * c2;
}

// ------------------------- encoder combine (+maxpool R=2, +relu) --------------
// Y[tau,n,o] = sum_{a,b,i} H[o][i][a][b] * Gb[(tau-a)%t][i][n]
// out[(tp*CO+o)*192+n] = relu(max(Y[2tp], Y[2tp+1]))
// G0 accessed via strides (so raw X works for layer e1). G1/G2 layout [tau][i][n].
template <int CI, int CO, int OT>
__global__ __launch_bounds__(NN) void combine_enc(
    const float* __restrict__ G0, int g0sT, int g0sI, int g0sN,
    const float* __restrict__ G1, const float* __restrict__ G2,
    const float* __restrict__ h, const float* __restrict__ s,
    float* __restrict__ out, int t)
{
    __shared__ float Hs[CI * 9 * OT];   // [((i*3+a)*3+b)*OT + oo]
    const int n  = threadIdx.x;
    const int tp = blockIdx.x;
    const int ob = blockIdx.y * OT;

    const float sv[4] = { s[0], s[1], s[2], s[3] };
    for (int idx = n; idx < CI * 9 * OT; idx += NN) {
        int oo = idx % OT;
        int tmp = idx / OT;
        int b = tmp % 3, a = (tmp / 3) % 3, i = tmp / 9;
        Hs[idx] = fold_H(&h[((ob + oo) * CI + i) * 3], sv, a, b);
    }
    __syncthreads();

    float acc0[OT], acc1[OT];
    #pragma unroll
    for (int o = 0; o < OT; o++) { acc0[o] = 0.f; acc1[o] = 0.f; }

    const int t0 = 2 * tp, t1 = 2 * tp + 1;
    #pragma unroll
    for (int a = 0; a < 3; a++) {
        int s0 = t0 - a; if (s0 < 0) s0 += t;
        int s1 = t1 - a; if (s1 < 0) s1 += t;
        #pragma unroll
        for (int i = 0; i < CI; i++) {
            float v00 = G0[s0 * g0sT + i * g0sI + n * g0sN];
            float v01 = G0[s1 * g0sT + i * g0sI + n * g0sN];
            float v10 = G1[(s0 * CI + i) * NN + n];
            float v11 = G1[(s1 * CI + i) * NN + n];
            float v20 = G2[(s0 * CI + i) * NN + n];
            float v21 = G2[(s1 * CI + i) * NN + n];
            const float* Hp = &Hs[(i * 3 + a) * 3 * OT];
            #pragma unroll
            for (int o = 0; o < OT; o++) {
                acc0[o] += Hp[o] * v00 + Hp[OT + o] * v10 + Hp[2 * OT + o] * v20;
                acc1[o] += Hp[o] * v01 + Hp[OT + o] * v11 + Hp[2 * OT + o] * v21;
            }
        }
    }
    #pragma unroll
    for (int o = 0; o < OT; o++) {
        float v = fmaxf(fmaxf(acc0[o], acc1[o]), 0.f);
        out[(tp * CO + (ob + o)) * NN + n] = v;
    }
}

// ------------------------- decoder combine (zero-stuffed input) ---------------
// Input lives at half time resolution: Gb[tl][i][n] represents full-res tau=2*tl;
// odd source timesteps are zero (from zero-stuffed upsampling), so skip them.
template <int CI, int CO, int OT, bool RELU, bool FINAL>
__global__ __launch_bounds__(NN) void combine_dec(
    const float* __restrict__ G0, const float* __restrict__ G1,
    const float* __restrict__ G2,
    const float* __restrict__ h, const float* __restrict__ s,
    float* __restrict__ out, int t)
{
    __shared__ float Hs[CI * 9 * OT];
    const int n   = threadIdx.x;
    const int tau = blockIdx.x;       // 0..t-1
    const int ob  = blockIdx.y * OT;

    const float sv[4] = { s[0], s[1], s[2], s[3] };
    for (int idx = n; idx < CI * 9 * OT; idx += NN) {
        int oo = idx % OT;
        int tmp = idx / OT;
        int b = tmp % 3, a = (tmp / 3) % 3, i = tmp / 9;
        Hs[idx] = fold_H(&h[((ob + oo) * CI + i) * 3], sv, a, b);
    }
    __syncthreads();

    float acc[OT];
    #pragma unroll
    for (int o = 0; o < OT; o++) acc[o] = 0.f;

    #pragma unroll
    for (int a = 0; a < 3; a++) {
        int src = tau - a; if (src < 0) src += t;
        if (src & 1) continue;          // zero-stuffed: odd timesteps are zero
        int tl = src >> 1;
        #pragma unroll
        for (int i = 0; i < CI; i++) {
            float v0 = G0[(tl * CI + i) * NN + n];
            float v1 = G1[(tl * CI + i) * NN + n];
            float v2 = G2[(tl * CI + i) * NN + n];
            const float* Hp = &Hs[(i * 3 + a) * 3 * OT];
            #pragma unroll
            for (int o = 0; o < OT; o++)
                acc[o] += Hp[o] * v0 + Hp[OT + o] * v1 + Hp[2 * OT + o] * v2;
        }
    }
    if (FINAL) {
        // output (N, T): out[n][tau] = Y[tau][n], CO == 1
        out[n * t + tau] = acc[0];
    } else {
        #pragma unroll
        for (int o = 0; o < OT; o++) {
            float v = acc[o];
            if (RELU) v = fmaxf(v, 0.f);
            out[(tau * CO + (ob + o)) * NN + n] = v;
        }
    }
}

// ------------------------- launch sequence ------------------------------------
extern "C" void kernel_launch(void* const* d_in, const int* in_sizes, int n_in,
                              void* d_out, int out_size)
{
    const float* X    = (const float*)d_in[0];  // (192, 32) row-major
    const float* Sg   = (const float*)d_in[1];  // (192, 192)
    const float* s    = (const float*)d_in[2];  // (2, 2)
    const float* h_e1 = (const float*)d_in[3];  // (16, 1, 3)
    const float* h_e2 = (const float*)d_in[4];  // (32, 16, 3)
    const float* h_d1 = (const float*)d_in[5];  // (16, 32, 3)
    const float* h_d2 = (const float*)d_in[6];  // (1, 16, 3)
    float* out = (float*)d_out;

    float *Sg2, *G1, *G2, *actA, *actB;
    cudaGetSymbolAddress((void**)&Sg2,  g_Sg2);
    cudaGetSymbolAddress((void**)&G1,   g_G1);
    cudaGetSymbolAddress((void**)&G2,   g_G2);
    cudaGetSymbolAddress((void**)&actA, g_actA);
    cudaGetSymbolAddress((void**)&actB, g_actB);

    const dim3 gb(16, 16);

    // 0) Sg2 = Sg @ Sg  (B row-major: sK=192, sJ=1; output row-major)
    gemm192<<<dim3(6, 6, 1), gb>>>(Sg, Sg, Sg, Sg2, Sg2, 192, NN, 1, NN, 1);

    // ---- encoder layer 1 (t=32, ci=1, co=16) ----
    // G1 = Sg @ X_cols, G2 = Sg2 @ X_cols; X[k=n][j=tau] = X[n*32+tau]
    gemm192<<<dim3(1, 6, 2), gb>>>(Sg, Sg2, X, G1, G2, 32, TT, 1, 1, NN);
    // combine + pool + relu -> actA [16t][16c][192n];  G0 = X via strides
    combine_enc<1, 16, 16><<<dim3(16, 1), NN>>>(X, 1, 0, TT, G1, G2, h_e1, s, actA, TT);

    // ---- encoder layer 2 (t=16, ci=16, co=32) ----
    gemm192<<<dim3(8, 6, 2), gb>>>(Sg, Sg2, actA, G1, G2, 256, 1, NN, 1, NN);
    combine_enc<16, 32, 4><<<dim3(8, 8), NN>>>(actA, 16 * NN, NN, 1, G1, G2, h_e2, s, actB, 16);

    // ---- decoder layer 1 (t=16, ci=32, co=16; input zero-stuffed from t=8) ----
    gemm192<<<dim3(8, 6, 2), gb>>>(Sg, Sg2, actB, G1, G2, 256, 1, NN, 1, NN);
    combine_dec<32, 16, 4, true, false><<<dim3(16, 4), NN>>>(actB, G1, G2, h_d1, s, actA, 16);

    // ---- decoder layer 2 (t=32, ci=16, co=1; input zero-stuffed from t=16) ----
    gemm192<<<dim3(8, 6, 2), gb>>>(Sg, Sg2, actA, G1, G2, 256, 1, NN, 1, NN);
    combine_dec<16, 1, 1, false, true><<<dim3(32, 1), NN>>>(actA, G1, G2, h_d2, s, out, TT);
}